// round 12
// baseline (speedup 1.0000x reference)
#include <cuda_runtime.h>
#include <cuda_fp16.h>
#include <mma.h>
using namespace nvcuda;

#define N_NODES   100000
#define N_EDGES   800000
#define N_ETYPES  5
#define IN_DIM    23
#define FP_STR    32
#define HID_DIM   128
#define OUT_DIM   64
#define NUM_GRAPHS 64
#define TOT_SEG   (N_ETYPES * N_NODES)          // 500000
#define TOT_EDGES (N_ETYPES * N_EDGES)          // 4000000
#define CAP       32                            // bucket = one 128B line

// ---------------- scratch (device globals; no allocation allowed) ----------
// INVARIANT: g_deg all-zero on entry (true at load; k_final restores it).
// INVARIANT: rows 120..127 of g_W1h are never written -> stay 0 (BSS).
__device__ unsigned int g_deg[TOT_SEG];                  // 2 MB
__device__ float  g_inv[TOT_SEG];                        // 2 MB
__device__ int    g_eidx[(size_t)TOT_SEG * CAP];         // 64 MB bucket CSR
__device__ __half g_feath[(size_t)N_NODES * FP_STR];     // 6.4 MB fp16 feat
__device__ __half g_W1h[128 * 128];                      // 32 KB padded W1
__device__ __half2 g_h1h[(size_t)N_NODES * 64];          // 25.6 MB h1 (fp16)
__device__ float  g_S[N_ETYPES * NUM_GRAPHS * HID_DIM];  // 160 KB
__device__ int    g_gstart[NUM_GRAPHS + 1];

// ---------------- kernel 0: one-pass bucket CSR build ----------------------
__global__ void k_build(const int* __restrict__ src, const int* __restrict__ dst) {
    int i = blockIdx.x * blockDim.x + threadIdx.x;
    if (i >= TOT_EDGES) return;
    int e   = i / N_EDGES;
    int seg = e * N_NODES + __ldg(dst + i);
    unsigned slot = atomicAdd(&g_deg[seg], 1u);
    if (slot < CAP) g_eidx[(size_t)seg * CAP + slot] = __ldg(src + i);
}

// ---------------- kernel 1: merged prep ------------------------------------
// fp16 feat pad, inv, padded fp16 W1, zero S, graph bounds. grid = 3.2M thr.
__global__ void k_prep(const float* __restrict__ feat, const float* __restrict__ W1,
                       const int* __restrict__ gid) {
    int i = blockIdx.x * blockDim.x + threadIdx.x;
    if (i < N_NODES * FP_STR) {
        int row = i >> 5, c = i & 31;
        g_feath[i] = __float2half((c < IN_DIM) ? __ldg(&feat[(size_t)row * IN_DIM + c]) : 0.f);
    }
    if (i < TOT_SEG) g_inv[i] = 1.0f / (float)(g_deg[i] + 1u);
    if (i < N_ETYPES * IN_DIM * HID_DIM) {
        int e = i / (IN_DIM * HID_DIM);
        int rem = i % (IN_DIM * HID_DIM);
        int c = rem / HID_DIM, n = rem % HID_DIM;
        g_W1h[(e * 24 + c) * HID_DIM + n] = __float2half(__ldg(W1 + i));
    }
    if (i < N_ETYPES * NUM_GRAPHS * HID_DIM) g_S[i] = 0.f;
    if (i < N_NODES) {
        int g = gid[i];
        if (i == 0) {
            for (int q = 0; q <= g; q++) g_gstart[q] = 0;
        } else {
            int gp = gid[i - 1];
            for (int q = gp + 1; q <= g; q++) g_gstart[q] = i;
        }
        if (i == N_NODES - 1)
            for (int q = g + 1; q <= NUM_GRAPHS; q++) g_gstart[q] = N_NODES;
    }
}

// ---------------- kernel 2: fused layer 1 (aggregate into smem + wmma) -----
// Block = 64 nodes. Phase 1: warp w aggregates nodes w*8..w*8+7 directly into
// the smem A tile (fp16 y rows). Phase 2: wmma h1 = relu(A @ W1_pad + bsum).
#define GM_NODES 64
#define AS_LD 136
__global__ void __launch_bounds__(256, 3) k_l1fused(const float* __restrict__ b1) {
    extern __shared__ char smraw[];
    __half* As = (__half*)smraw;                 // 64 x 136 = 17408 B
    __half* Bs = As + 64 * AS_LD;                // 128 x 136 = 34816 B
    float*  Cst = (float*)smraw;                 // 64 x 128 f32 (reuse after mma)
    __shared__ float bs[HID_DIM];
    int tid  = threadIdx.x;
    int lane = tid & 31;
    int w    = tid >> 5;
    int nb   = blockIdx.x * GM_NODES;

    // zero A tile (pad cols must be 0), load B tile + bias
    for (int q = tid; q < 64 * AS_LD / 8; q += 256)
        *(uint4*)(As + q * 8) = make_uint4(0u, 0u, 0u, 0u);
    for (int q = tid; q < 128 * 16; q += 256) {
        int r = q >> 4, sg = q & 15;
        *(uint4*)(Bs + r * AS_LD + sg * 8) = *(const uint4*)(g_W1h + r * 128 + sg * 8);
    }
    if (tid < HID_DIM) {
        float s = 0.f;
#pragma unroll
        for (int e = 0; e < N_ETYPES; e++) s += b1[e * HID_DIM + tid];
        bs[tid] = s;
    }
    __syncthreads();

    // Phase 1: aggregation, warp per node (8 nodes serial per warp)
    for (int j = 0; j < 8; j++) {
        int r = w * 8 + j;
        int i = nb + r;
        if (i >= N_NODES) break;
        float fself = __half2float(g_feath[((size_t)i << 5) + lane]);  // 0 lane>=23

        int   len[N_ETYPES];
        float ivv[N_ETYPES];
        int4  hd[N_ETYPES], hd2[N_ETYPES];
#pragma unroll
        for (int e = 0; e < N_ETYPES; e++) {
            int seg = e * N_NODES + i;
            len[e] = min((int)g_deg[seg], CAP);
            ivv[e] = g_inv[seg];
            const int4* row = (const int4*)(g_eidx + (size_t)seg * CAP);
            hd[e]  = __ldg(row);
            hd2[e] = __ldg(row + 1);              // CAP=32 row: always in-bounds
        }
#pragma unroll
        for (int e = 0; e < N_ETYPES; e++) {
            const int* lst = g_eidx + (size_t)(e * N_NODES + i) * CAP;
            int l  = len[e];
            int l4 = l & ~3;
            float s0 = 0.f, s1 = 0.f, s2 = 0.f, s3 = 0.f;
            int4 v = hd[e], vn = hd2[e];
            for (int k = 0; k < l4; k += 4) {
                int4 nx = vn;
                if (k + 8 < l4) vn = __ldg((const int4*)(lst + k + 8));
                s0 += __half2float(g_feath[((size_t)v.x << 5) + lane]);
                s1 += __half2float(g_feath[((size_t)v.y << 5) + lane]);
                s2 += __half2float(g_feath[((size_t)v.z << 5) + lane]);
                s3 += __half2float(g_feath[((size_t)v.w << 5) + lane]);
                v = nx;
            }
            for (int k = l4; k < l; k++)
                s0 += __half2float(g_feath[((size_t)__ldg(lst + k) << 5) + lane]);
            float yv = ((s0 + s1) + (s2 + s3) + fself) * ivv[e];
            if (lane < IN_DIM)
                As[r * AS_LD + e * 24 + lane] = __float2half(yv);
        }
    }
    __syncthreads();

    // Phase 2: wmma — warp tile 16x64 (4 frags), K=128
    int rowB = (w >> 1) * 16;
    int colB = (w & 1) * 64;
    wmma::fragment<wmma::accumulator, 16, 16, 16, float> c[4];
#pragma unroll
    for (int j = 0; j < 4; j++) wmma::fill_fragment(c[j], 0.f);
#pragma unroll
    for (int k0 = 0; k0 < 8; k0++) {
        wmma::fragment<wmma::matrix_a, 16, 16, 16, __half, wmma::row_major> a;
        wmma::load_matrix_sync(a, As + rowB * AS_LD + k0 * 16, AS_LD);
#pragma unroll
        for (int j = 0; j < 4; j++) {
            wmma::fragment<wmma::matrix_b, 16, 16, 16, __half, wmma::row_major> b;
            wmma::load_matrix_sync(b, Bs + (k0 * 16) * AS_LD + colB + j * 16, AS_LD);
            wmma::mma_sync(c[j], a, b, c[j]);
        }
    }
    __syncthreads();                              // done reading As/Bs
#pragma unroll
    for (int j = 0; j < 4; j++)
        wmma::store_matrix_sync(Cst + rowB * 128 + colB + j * 16, c[j], 128,
                                wmma::mem_row_major);
    __syncthreads();
    // epilogue: bias + relu + pack fp16
    for (int q = tid; q < 64 * 64; q += 256) {    // half2 units
        int r = q >> 6, p = q & 63;
        int node = nb + r;
        if (node >= N_NODES) continue;
        float v0 = fmaxf(Cst[r * 128 + 2 * p]     + bs[2 * p],     0.f);
        float v1 = fmaxf(Cst[r * 128 + 2 * p + 1] + bs[2 * p + 1], 0.f);
        g_h1h[((size_t)node << 6) + p] = __floats2half2_rn(v0, v1);
    }
}

// ---------------- kernel 3 (PROFILED): layer 2 -----------------------------
#define L2CH 32
__global__ void __launch_bounds__(256, 3) k_layer2(const int* __restrict__ gid) {
    __shared__ float sacc[8][N_ETYPES * HID_DIM];   // 20 KB
    int tid  = threadIdx.x;
    int lane = tid & 31;
    int w    = tid >> 5;
    int start = blockIdx.x * L2CH;
    int end   = min(start + L2CH, N_NODES);
    int g0 = gid[start];
    bool multi = (gid[end - 1] != g0);

    float4 acc[N_ETYPES];
#pragma unroll
    for (int e = 0; e < N_ETYPES; e++) acc[e] = make_float4(0.f, 0.f, 0.f, 0.f);
    int gcur = g0;

    for (int i = start + w; i < end; i += 8) {
        int g = gid[i];
        if (multi && g != gcur) {
#pragma unroll
            for (int e = 0; e < N_ETYPES; e++) {
                float* p = g_S + (size_t)(e * NUM_GRAPHS + gcur) * HID_DIM + lane * 4;
                if (acc[e].x != 0.f) atomicAdd(p + 0, acc[e].x);
                if (acc[e].y != 0.f) atomicAdd(p + 1, acc[e].y);
                if (acc[e].z != 0.f) atomicAdd(p + 2, acc[e].z);
                if (acc[e].w != 0.f) atomicAdd(p + 3, acc[e].w);
                acc[e] = make_float4(0.f, 0.f, 0.f, 0.f);
            }
            gcur = g;
        }
        uint2 rs = *(const uint2*)(g_h1h + ((size_t)i << 6) + lane * 2);
        __half2 self0 = *(__half2*)&rs.x;
        __half2 self1 = *(__half2*)&rs.y;

        int   len[N_ETYPES];
        float ivv[N_ETYPES];
        int4  hd[N_ETYPES], hd2[N_ETYPES];
#pragma unroll
        for (int e = 0; e < N_ETYPES; e++) {
            int seg = e * N_NODES + i;
            len[e] = min((int)g_deg[seg], CAP);
            ivv[e] = g_inv[seg];
            const int4* row = (const int4*)(g_eidx + (size_t)seg * CAP);
            hd[e]  = __ldg(row);
            hd2[e] = __ldg(row + 1);
        }
#pragma unroll
        for (int e = 0; e < N_ETYPES; e++) {
            const int* lst = g_eidx + (size_t)(e * N_NODES + i) * CAP;
            int l  = len[e];
            int l4 = l & ~3;
            __half2 u0 = self0, u1 = self1;
            int4 v = hd[e], vn = hd2[e];
            for (int k = 0; k < l4; k += 4) {
                int4 nx = vn;
                if (k + 8 < l4) vn = __ldg((const int4*)(lst + k + 8));
                uint2 ra = *(const uint2*)(g_h1h + ((size_t)v.x << 6) + lane * 2);
                uint2 rb = *(const uint2*)(g_h1h + ((size_t)v.y << 6) + lane * 2);
                uint2 rc = *(const uint2*)(g_h1h + ((size_t)v.z << 6) + lane * 2);
                uint2 rd = *(const uint2*)(g_h1h + ((size_t)v.w << 6) + lane * 2);
                __half2 pa = __hadd2(*(__half2*)&ra.x, *(__half2*)&rb.x);
                __half2 pb = __hadd2(*(__half2*)&rc.x, *(__half2*)&rd.x);
                __half2 qa = __hadd2(*(__half2*)&ra.y, *(__half2*)&rb.y);
                __half2 qb = __hadd2(*(__half2*)&rc.y, *(__half2*)&rd.y);
                u0 = __hadd2(u0, __hadd2(pa, pb));
                u1 = __hadd2(u1, __hadd2(qa, qb));
                v = nx;
            }
            for (int k = l4; k < l; k++) {
                int a = __ldg(lst + k);
                uint2 ra = *(const uint2*)(g_h1h + ((size_t)a << 6) + lane * 2);
                u0 = __hadd2(u0, *(__half2*)&ra.x);
                u1 = __hadd2(u1, *(__half2*)&ra.y);
            }
            float2 f0 = __half22float2(u0);
            float2 f1 = __half22float2(u1);
            float iv = ivv[e];
            acc[e].x = fmaf(f0.x, iv, acc[e].x);
            acc[e].y = fmaf(f0.y, iv, acc[e].y);
            acc[e].z = fmaf(f1.x, iv, acc[e].z);
            acc[e].w = fmaf(f1.y, iv, acc[e].w);
        }
    }

    if (multi) {
#pragma unroll
        for (int e = 0; e < N_ETYPES; e++) {
            float* p = g_S + (size_t)(e * NUM_GRAPHS + gcur) * HID_DIM + lane * 4;
            if (acc[e].x != 0.f) atomicAdd(p + 0, acc[e].x);
            if (acc[e].y != 0.f) atomicAdd(p + 1, acc[e].y);
            if (acc[e].z != 0.f) atomicAdd(p + 2, acc[e].z);
            if (acc[e].w != 0.f) atomicAdd(p + 3, acc[e].w);
        }
    } else {
#pragma unroll
        for (int e = 0; e < N_ETYPES; e++)
            *(float4*)&sacc[w][e * HID_DIM + lane * 4] = acc[e];
        __syncthreads();
        for (int q = tid; q < N_ETYPES * HID_DIM; q += 256) {
            float s = 0.f;
#pragma unroll
            for (int w2 = 0; w2 < 8; w2++) s += sacc[w2][q];
            if (s != 0.f) {
                int e = q >> 7, d = q & 127;
                atomicAdd(&g_S[(size_t)(e * NUM_GRAPHS + g0) * HID_DIM + d], s);
            }
        }
    }
}

// ---------------- kernel 4: finisher + restore deg==0 invariant ------------
#define FIN_BLOCKS 576
__global__ void k_final(const float* __restrict__ W2, const float* __restrict__ b2,
                        float* __restrict__ out) {
    int g = blockIdx.x;
    int o = threadIdx.x;
    if (g < NUM_GRAPHS) {
        __shared__ float Ss[HID_DIM];
        float a = 0.f;
        for (int e = 0; e < N_ETYPES; e++) {
            __syncthreads();
            if (o < HID_DIM) Ss[o] = g_S[(e * NUM_GRAPHS + g) * HID_DIM + o];
            __syncthreads();
            if (o < OUT_DIM) {
                const float* We = W2 + (size_t)e * HID_DIM * OUT_DIM;
#pragma unroll 4
                for (int k = 0; k < HID_DIM; k++)
                    a = fmaf(Ss[k], We[k * OUT_DIM + o], a);
            }
        }
        if (o < OUT_DIM) {
            int cnt = g_gstart[g + 1] - g_gstart[g];
            float bsum = 0.f;
#pragma unroll
            for (int e = 0; e < N_ETYPES; e++) bsum += b2[e * OUT_DIM + o];
            out[g * OUT_DIM + o] = (cnt > 0) ? (a / (float)cnt + bsum) : 0.f;
        }
    }
    for (int q = blockIdx.x * blockDim.x + threadIdx.x; q < TOT_SEG;
         q += FIN_BLOCKS * blockDim.x)
        g_deg[q] = 0u;
}

// ---------------- launcher ---------------------------------------------------
extern "C" void kernel_launch(void* const* d_in, const int* in_sizes, int n_in,
                              void* d_out, int out_size) {
    const float* feat = (const float*)d_in[0];
    const int*   src  = (const int*)  d_in[1];
    const int*   dst  = (const int*)  d_in[2];
    const int*   gid  = (const int*)  d_in[3];
    const float* W1   = (const float*)d_in[4];
    const float* b1   = (const float*)d_in[5];
    const float* W2   = (const float*)d_in[6];
    const float* b2   = (const float*)d_in[7];
    float* out = (float*)d_out;

    k_build<<<(TOT_EDGES + 255) / 256, 256>>>(src, dst);               // 0
    k_prep<<<(N_NODES * FP_STR + 255) / 256, 256>>>(feat, W1, gid);    // 1

    int gsm = 64 * AS_LD * 2 + 128 * AS_LD * 2;                        // 52224 B
    cudaFuncSetAttribute(k_l1fused, cudaFuncAttributeMaxDynamicSharedMemorySize, gsm);
    k_l1fused<<<(N_NODES + GM_NODES - 1) / GM_NODES, 256, gsm>>>(b1);  // 2

    k_layer2<<<(N_NODES + L2CH - 1) / L2CH, 256>>>(gid);               // 3 (profiled)
    k_final<<<FIN_BLOCKS, 128>>>(W2, b2, out);                         // 4
}

// round 13
// speedup vs baseline: 1.1512x; 1.1512x over previous
#include <cuda_runtime.h>
#include <cuda_fp16.h>
#include <mma.h>
using namespace nvcuda;

#define N_NODES   100000
#define N_EDGES   800000
#define N_ETYPES  5
#define IN_DIM    23
#define FP_STR    32
#define HID_DIM   128
#define OUT_DIM   64
#define NUM_GRAPHS 64
#define TOT_SEG   (N_ETYPES * N_NODES)          // 500000
#define TOT_EDGES (N_ETYPES * N_EDGES)          // 4000000
#define CAP       32                            // bucket = one 128B line

// ---------------- scratch (device globals; no allocation allowed) ----------
// INVARIANT: g_deg all-zero on entry (true at load; k_final restores it).
// INVARIANT: cols 120..127 of g_y and rows 120..127 of g_W1h never written -> 0.
__device__ unsigned int g_deg[TOT_SEG];                  // 2 MB
__device__ float  g_inv[TOT_SEG];                        // 2 MB
__device__ int    g_eidx[(size_t)TOT_SEG * CAP];         // 64 MB bucket CSR
__device__ __half g_feath[(size_t)N_NODES * FP_STR];     // 6.4 MB fp16 feat
__device__ __half g_y[(size_t)N_NODES * 128];            // 25.6 MB padded y
__device__ __half g_W1h[128 * 128];                      // 32 KB padded W1
__device__ __half2 g_h1h[(size_t)N_NODES * 64];          // 25.6 MB h1 (fp16)
__device__ float  g_S[N_ETYPES * NUM_GRAPHS * HID_DIM];  // 160 KB
__device__ int    g_gstart[NUM_GRAPHS + 1];

// ---------------- kernel 0: one-pass bucket CSR build ----------------------
__global__ void k_build(const int* __restrict__ src, const int* __restrict__ dst) {
    int i = blockIdx.x * blockDim.x + threadIdx.x;
    if (i >= TOT_EDGES) return;
    int e   = i / N_EDGES;
    int seg = e * N_NODES + __ldg(dst + i);
    unsigned slot = atomicAdd(&g_deg[seg], 1u);
    if (slot < CAP) g_eidx[(size_t)seg * CAP + slot] = __ldg(src + i);
}

// ---------------- kernel 1: prep A (inv + bounds + zero S) -----------------
__global__ void k_prepA(const int* __restrict__ gid) {
    int i = blockIdx.x * blockDim.x + threadIdx.x;
    if (i < TOT_SEG) g_inv[i] = 1.0f / (float)(g_deg[i] + 1u);
    if (i < N_ETYPES * NUM_GRAPHS * HID_DIM) g_S[i] = 0.f;
    if (i < N_NODES) {
        int g = gid[i];
        if (i == 0) {
            for (int q = 0; q <= g; q++) g_gstart[q] = 0;
        } else {
            int gp = gid[i - 1];
            for (int q = gp + 1; q <= g; q++) g_gstart[q] = i;
        }
        if (i == N_NODES - 1)
            for (int q = g + 1; q <= NUM_GRAPHS; q++) g_gstart[q] = N_NODES;
    }
}

// ---------------- kernel 2: prep B (fp16 feat pad + fp16 padded W1) --------
__global__ void k_prepB(const float* __restrict__ feat, const float* __restrict__ W1) {
    int q = blockIdx.x * blockDim.x + threadIdx.x;
    if (q < N_NODES * FP_STR) {
        int row = q >> 5, c = q & 31;
        g_feath[q] = __float2half((c < IN_DIM) ? __ldg(&feat[(size_t)row * IN_DIM + c]) : 0.f);
    }
    if (q < N_ETYPES * IN_DIM * HID_DIM) {
        int e = q / (IN_DIM * HID_DIM);
        int rem = q % (IN_DIM * HID_DIM);
        int c = rem / HID_DIM, n = rem % HID_DIM;
        g_W1h[(e * 24 + c) * HID_DIM + n] = __float2half(__ldg(W1 + q));
    }
}

// ---------------- kernel 3 (PROFILED): aggregate gather, pair scheme -------
// Warp per node. Lanes 0-15 process edge A, 16-31 edge B; each lane loads
// half2 (2 dims). Per 4 edges: 2 warp LDGs. shfl_down(16) combine per seg.
__global__ void __launch_bounds__(256) k_agg() {
    int lane = threadIdx.x & 31;
    int i = (blockIdx.x * blockDim.x + threadIdx.x) >> 5;
    if (i >= N_NODES) return;
    int hid = lane >> 4;          // 0 = edge A, 1 = edge B
    int hl  = lane & 15;          // owns dims 2*hl, 2*hl+1
    float2 fself = __half22float2(
        *(const __half2*)(g_feath + ((size_t)i << 5) + (hl << 1)));

    int   len[N_ETYPES];
    float ivv[N_ETYPES];
    int4  hd[N_ETYPES];
#pragma unroll
    for (int e = 0; e < N_ETYPES; e++) {
        int seg = e * N_NODES + i;
        len[e] = min((int)g_deg[seg], CAP);
        ivv[e] = g_inv[seg];
        hd[e]  = __ldg((const int4*)(g_eidx + (size_t)seg * CAP));
    }
#pragma unroll
    for (int e = 0; e < N_ETYPES; e++) {
        const int* lst = g_eidx + (size_t)(e * N_NODES + i) * CAP;
        int l  = len[e];
        int l4 = l & ~3;
        float2 s = make_float2(0.f, 0.f);
        int4 v = hd[e];
        for (int k = 0; k < l4; k += 4) {
            int4 nv;
            if (k + 4 < l4) nv = __ldg((const int4*)(lst + k + 4));
            int ia = hid ? v.y : v.x;
            int ib = hid ? v.w : v.z;
            float2 fa = __half22float2(
                *(const __half2*)(g_feath + ((size_t)ia << 5) + (hl << 1)));
            float2 fb = __half22float2(
                *(const __half2*)(g_feath + ((size_t)ib << 5) + (hl << 1)));
            s.x += fa.x + fb.x;
            s.y += fa.y + fb.y;
            v = nv;
        }
        for (int k = l4; k < l; k += 2) {
            int ea = __ldg(lst + k);
            bool bv = (k + 1 < l);
            int eb = bv ? __ldg(lst + k + 1) : ea;
            int idx = hid ? eb : ea;
            float2 f = __half22float2(
                *(const __half2*)(g_feath + ((size_t)idx << 5) + (hl << 1)));
            if (hid && !bv) { f.x = 0.f; f.y = 0.f; }
            s.x += f.x; s.y += f.y;
        }
        s.x += __shfl_down_sync(0xffffffffu, s.x, 16);
        s.y += __shfl_down_sync(0xffffffffu, s.y, 16);
        if (lane < 12) {   // dims 0..23 of this etype's 24-col slot
            float y0 = (s.x + fself.x) * ivv[e];
            float y1 = (s.y + fself.y) * ivv[e];
            *(__half2*)(g_y + ((size_t)i << 7) + e * 24 + (lane << 1)) =
                __floats2half2_rn(y0, y1);
        }
    }
}

// ---------------- kernel 4: layer-1 GEMM via wmma --------------------------
#define GM_NODES 64
#define AS_LD 136
__global__ void __launch_bounds__(256) k_gemm(const float* __restrict__ b1) {
    extern __shared__ char smraw[];
    __half* As = (__half*)smraw;                 // 64 x 136
    __half* Bs = As + 64 * AS_LD;                // 128 x 136
    float*  Cst = (float*)smraw;                 // 64 x 128 f32 (reuse)
    __shared__ float bs[HID_DIM];
    int tid = threadIdx.x;
    int nb  = blockIdx.x * GM_NODES;

    if (tid < HID_DIM) {
        float s = 0.f;
#pragma unroll
        for (int e = 0; e < N_ETYPES; e++) s += b1[e * HID_DIM + tid];
        bs[tid] = s;
    }
    for (int q = tid; q < 64 * 16; q += 256) {
        int r = q >> 4, sg = q & 15;
        uint4 v = make_uint4(0u, 0u, 0u, 0u);
        int node = nb + r;
        if (node < N_NODES) v = *(const uint4*)(g_y + ((size_t)node << 7) + sg * 8);
        *(uint4*)(As + r * AS_LD + sg * 8) = v;
    }
    for (int q = tid; q < 128 * 16; q += 256) {
        int r = q >> 4, sg = q & 15;
        *(uint4*)(Bs + r * AS_LD + sg * 8) = *(const uint4*)(g_W1h + r * 128 + sg * 8);
    }
    __syncthreads();

    int w    = tid >> 5;
    int rowB = (w >> 1) * 16;
    int colB = (w & 1) * 64;
    wmma::fragment<wmma::accumulator, 16, 16, 16, float> c[4];
#pragma unroll
    for (int j = 0; j < 4; j++) wmma::fill_fragment(c[j], 0.f);
#pragma unroll
    for (int k0 = 0; k0 < 8; k0++) {
        wmma::fragment<wmma::matrix_a, 16, 16, 16, __half, wmma::row_major> a;
        wmma::load_matrix_sync(a, As + rowB * AS_LD + k0 * 16, AS_LD);
#pragma unroll
        for (int j = 0; j < 4; j++) {
            wmma::fragment<wmma::matrix_b, 16, 16, 16, __half, wmma::row_major> b;
            wmma::load_matrix_sync(b, Bs + (k0 * 16) * AS_LD + colB + j * 16, AS_LD);
            wmma::mma_sync(c[j], a, b, c[j]);
        }
    }
    __syncthreads();
#pragma unroll
    for (int j = 0; j < 4; j++)
        wmma::store_matrix_sync(Cst + rowB * 128 + colB + j * 16, c[j], 128,
                                wmma::mem_row_major);
    __syncthreads();
    for (int q = tid; q < 64 * 64; q += 256) {
        int r = q >> 6, p = q & 63;
        int node = nb + r;
        if (node >= N_NODES) continue;
        float v0 = fmaxf(Cst[r * 128 + 2 * p]     + bs[2 * p],     0.f);
        float v1 = fmaxf(Cst[r * 128 + 2 * p + 1] + bs[2 * p + 1], 0.f);
        g_h1h[((size_t)node << 6) + p] = __floats2half2_rn(v0, v1);
    }
}

// ---------------- kernel 5: layer 2 — hadd2, forced 4 blocks/SM ------------
#define L2CH 64
__global__ void __launch_bounds__(256, 4) k_layer2(const int* __restrict__ gid) {
    __shared__ float sacc[8][N_ETYPES * HID_DIM];   // 20 KB
    int tid  = threadIdx.x;
    int lane = tid & 31;
    int w    = tid >> 5;
    int start = blockIdx.x * L2CH;
    int end   = min(start + L2CH, N_NODES);
    int g0 = gid[start];
    bool multi = (gid[end - 1] != g0);

    float4 acc[N_ETYPES];
#pragma unroll
    for (int e = 0; e < N_ETYPES; e++) acc[e] = make_float4(0.f, 0.f, 0.f, 0.f);
    int gcur = g0;

    for (int i = start + w; i < end; i += 8) {
        int g = gid[i];
        if (multi && g != gcur) {
#pragma unroll
            for (int e = 0; e < N_ETYPES; e++) {
                float* p = g_S + (size_t)(e * NUM_GRAPHS + gcur) * HID_DIM + lane * 4;
                if (acc[e].x != 0.f) atomicAdd(p + 0, acc[e].x);
                if (acc[e].y != 0.f) atomicAdd(p + 1, acc[e].y);
                if (acc[e].z != 0.f) atomicAdd(p + 2, acc[e].z);
                if (acc[e].w != 0.f) atomicAdd(p + 3, acc[e].w);
                acc[e] = make_float4(0.f, 0.f, 0.f, 0.f);
            }
            gcur = g;
        }
        uint2 rs = *(const uint2*)(g_h1h + ((size_t)i << 6) + lane * 2);
        __half2 self0 = *(__half2*)&rs.x;
        __half2 self1 = *(__half2*)&rs.y;

        int   len[N_ETYPES];
        float ivv[N_ETYPES];
        int4  hd[N_ETYPES];
#pragma unroll
        for (int e = 0; e < N_ETYPES; e++) {
            int seg = e * N_NODES + i;
            len[e] = min((int)g_deg[seg], CAP);
            ivv[e] = g_inv[seg];
            hd[e]  = __ldg((const int4*)(g_eidx + (size_t)seg * CAP));
        }
#pragma unroll
        for (int e = 0; e < N_ETYPES; e++) {
            const int* lst = g_eidx + (size_t)(e * N_NODES + i) * CAP;
            int l  = len[e];
            int l4 = l & ~3;
            __half2 u0 = self0, u1 = self1;
            int4 v = hd[e];
            for (int k = 0; k < l4; k += 4) {
                int4 nv;
                if (k + 4 < l4) nv = __ldg((const int4*)(lst + k + 4));
                uint2 ra = *(const uint2*)(g_h1h + ((size_t)v.x << 6) + lane * 2);
                uint2 rb = *(const uint2*)(g_h1h + ((size_t)v.y << 6) + lane * 2);
                uint2 rc = *(const uint2*)(g_h1h + ((size_t)v.z << 6) + lane * 2);
                uint2 rd = *(const uint2*)(g_h1h + ((size_t)v.w << 6) + lane * 2);
                __half2 pa = __hadd2(*(__half2*)&ra.x, *(__half2*)&rb.x);
                __half2 pb = __hadd2(*(__half2*)&rc.x, *(__half2*)&rd.x);
                __half2 qa = __hadd2(*(__half2*)&ra.y, *(__half2*)&rb.y);
                __half2 qb = __hadd2(*(__half2*)&rc.y, *(__half2*)&rd.y);
                u0 = __hadd2(u0, __hadd2(pa, pb));
                u1 = __hadd2(u1, __hadd2(qa, qb));
                v = nv;
            }
            for (int k = l4; k < l; k++) {
                int a = __ldg(lst + k);
                uint2 ra = *(const uint2*)(g_h1h + ((size_t)a << 6) + lane * 2);
                u0 = __hadd2(u0, *(__half2*)&ra.x);
                u1 = __hadd2(u1, *(__half2*)&ra.y);
            }
            float2 f0 = __half22float2(u0);
            float2 f1 = __half22float2(u1);
            float iv = ivv[e];
            acc[e].x = fmaf(f0.x, iv, acc[e].x);
            acc[e].y = fmaf(f0.y, iv, acc[e].y);
            acc[e].z = fmaf(f1.x, iv, acc[e].z);
            acc[e].w = fmaf(f1.y, iv, acc[e].w);
        }
    }

    if (multi) {
#pragma unroll
        for (int e = 0; e < N_ETYPES; e++) {
            float* p = g_S + (size_t)(e * NUM_GRAPHS + gcur) * HID_DIM + lane * 4;
            if (acc[e].x != 0.f) atomicAdd(p + 0, acc[e].x);
            if (acc[e].y != 0.f) atomicAdd(p + 1, acc[e].y);
            if (acc[e].z != 0.f) atomicAdd(p + 2, acc[e].z);
            if (acc[e].w != 0.f) atomicAdd(p + 3, acc[e].w);
        }
    } else {
#pragma unroll
        for (int e = 0; e < N_ETYPES; e++)
            *(float4*)&sacc[w][e * HID_DIM + lane * 4] = acc[e];
        __syncthreads();
        for (int q = tid; q < N_ETYPES * HID_DIM; q += 256) {
            float s = 0.f;
#pragma unroll
            for (int w2 = 0; w2 < 8; w2++) s += sacc[w2][q];
            if (s != 0.f) {
                int e = q >> 7, d = q & 127;
                atomicAdd(&g_S[(size_t)(e * NUM_GRAPHS + g0) * HID_DIM + d], s);
            }
        }
    }
}

// ---------------- kernel 6: finisher + restore deg==0 invariant ------------
#define FIN_BLOCKS 576
__global__ void k_final(const float* __restrict__ W2, const float* __restrict__ b2,
                        float* __restrict__ out) {
    int g = blockIdx.x;
    int o = threadIdx.x;
    if (g < NUM_GRAPHS) {
        __shared__ float Ss[HID_DIM];
        float a = 0.f;
        for (int e = 0; e < N_ETYPES; e++) {
            __syncthreads();
            if (o < HID_DIM) Ss[o] = g_S[(e * NUM_GRAPHS + g) * HID_DIM + o];
            __syncthreads();
            if (o < OUT_DIM) {
                const float* We = W2 + (size_t)e * HID_DIM * OUT_DIM;
#pragma unroll 4
                for (int k = 0; k < HID_DIM; k++)
                    a = fmaf(Ss[k], We[k * OUT_DIM + o], a);
            }
        }
        if (o < OUT_DIM) {
            int cnt = g_gstart[g + 1] - g_gstart[g];
            float bsum = 0.f;
#pragma unroll
            for (int e = 0; e < N_ETYPES; e++) bsum += b2[e * OUT_DIM + o];
            out[g * OUT_DIM + o] = (cnt > 0) ? (a / (float)cnt + bsum) : 0.f;
        }
    }
    for (int q = blockIdx.x * blockDim.x + threadIdx.x; q < TOT_SEG;
         q += FIN_BLOCKS * blockDim.x)
        g_deg[q] = 0u;
}

// ---------------- launcher ---------------------------------------------------
extern "C" void kernel_launch(void* const* d_in, const int* in_sizes, int n_in,
                              void* d_out, int out_size) {
    const float* feat = (const float*)d_in[0];
    const int*   src  = (const int*)  d_in[1];
    const int*   dst  = (const int*)  d_in[2];
    const int*   gid  = (const int*)  d_in[3];
    const float* W1   = (const float*)d_in[4];
    const float* b1   = (const float*)d_in[5];
    const float* W2   = (const float*)d_in[6];
    const float* b2   = (const float*)d_in[7];
    float* out = (float*)d_out;

    k_build<<<(TOT_EDGES + 255) / 256, 256>>>(src, dst);          // 0
    k_prepA<<<(TOT_SEG + 255) / 256, 256>>>(gid);                 // 1
    k_prepB<<<(N_NODES * FP_STR + 255) / 256, 256>>>(feat, W1);   // 2
    k_agg<<<(N_NODES * 32 + 255) / 256, 256>>>();                 // 3 (profiled)

    int gsm = 64 * AS_LD * 2 + 128 * AS_LD * 2;                   // 52224 B
    cudaFuncSetAttribute(k_gemm, cudaFuncAttributeMaxDynamicSharedMemorySize, gsm);
    k_gemm<<<(N_NODES + GM_NODES - 1) / GM_NODES, 256, gsm>>>(b1);// 4

    k_layer2<<<(N_NODES + L2CH - 1) / L2CH, 256>>>(gid);          // 5
    k_final<<<FIN_BLOCKS, 128>>>(W2, b2, out);                    // 6
}

// round 17
// speedup vs baseline: 1.2477x; 1.0838x over previous
#include <cuda_runtime.h>
#include <cuda_fp16.h>
#include <cuda_fp8.h>
#include <mma.h>
using namespace nvcuda;

#define N_NODES   100000
#define N_EDGES   800000
#define N_ETYPES  5
#define IN_DIM    23
#define FP_STR    32
#define HID_DIM   128
#define OUT_DIM   64
#define NUM_GRAPHS 64
#define TOT_SEG   (N_ETYPES * N_NODES)          // 500000
#define TOT_EDGES (N_ETYPES * N_EDGES)          // 4000000
#define CAP       32                            // bucket = one 128B line

// ---------------- scratch (device globals; no allocation allowed) ----------
// INVARIANT: g_deg all-zero on entry (true at load; k_final restores it).
// INVARIANT: cols 120..127 of g_y and rows 120..127 of g_W1h never written -> 0.
__device__ unsigned int g_deg[TOT_SEG];                  // 2 MB
__device__ int    g_eidx[(size_t)TOT_SEG * CAP];         // 64 MB bucket CSR
__device__ __half g_feath[(size_t)N_NODES * FP_STR];     // 6.4 MB fp16 feat
__device__ __half g_y[(size_t)N_NODES * 128];            // 25.6 MB padded y
__device__ __half g_W1h[128 * 128];                      // 32 KB padded W1
__device__ unsigned g_h1b[(size_t)N_NODES * 32];         // 12.8 MB h1 (fp8 e4m3)
__device__ float  g_S[N_ETYPES * NUM_GRAPHS * HID_DIM];  // 160 KB
__device__ int    g_gstart[NUM_GRAPHS + 1];

__device__ __forceinline__ void fp8x4_to_h2(unsigned w, __half2& lo, __half2& hi) {
    __half2_raw l = __nv_cvt_fp8x2_to_halfraw2((__nv_fp8x2_storage_t)(w & 0xFFFFu), __NV_E4M3);
    __half2_raw h = __nv_cvt_fp8x2_to_halfraw2((__nv_fp8x2_storage_t)(w >> 16), __NV_E4M3);
    lo = *(__half2*)&l;
    hi = *(__half2*)&h;
}

// ---------------- kernel 0: build CSR + all prep in one launch -------------
__global__ void k_build(const int* __restrict__ src, const int* __restrict__ dst,
                        const float* __restrict__ feat, const float* __restrict__ W1,
                        const int* __restrict__ gid) {
    int i = blockIdx.x * blockDim.x + threadIdx.x;
    if (i < TOT_EDGES) {
        int e   = i / N_EDGES;
        int seg = e * N_NODES + __ldg(dst + i);
        unsigned slot = atomicAdd(&g_deg[seg], 1u);
        if (slot < CAP) g_eidx[(size_t)seg * CAP + slot] = __ldg(src + i);
    }
    if (i < N_NODES * FP_STR) {
        int row = i >> 5, c = i & 31;
        g_feath[i] = __float2half((c < IN_DIM) ? __ldg(&feat[(size_t)row * IN_DIM + c]) : 0.f);
    }
    if (i < N_ETYPES * IN_DIM * HID_DIM) {
        int e = i / (IN_DIM * HID_DIM);
        int rem = i % (IN_DIM * HID_DIM);
        int c = rem / HID_DIM, n = rem % HID_DIM;
        g_W1h[(e * 24 + c) * HID_DIM + n] = __float2half(__ldg(W1 + i));
    }
    if (i < N_ETYPES * NUM_GRAPHS * HID_DIM) g_S[i] = 0.f;
    if (i < N_NODES) {
        int g = gid[i];
        if (i == 0) {
            for (int q = 0; q <= g; q++) g_gstart[q] = 0;
        } else {
            int gp = gid[i - 1];
            for (int q = gp + 1; q <= g; q++) g_gstart[q] = i;
        }
        if (i == N_NODES - 1)
            for (int q = g + 1; q <= NUM_GRAPHS; q++) g_gstart[q] = N_NODES;
    }
}

// ---------------- kernel 1: aggregate gather, pair scheme ------------------
// Warp per node. Lanes 0-15 edge A, 16-31 edge B; each lane loads half2.
// inv computed inline from g_deg.
__global__ void __launch_bounds__(256) k_agg() {
    int lane = threadIdx.x & 31;
    int i = (blockIdx.x * blockDim.x + threadIdx.x) >> 5;
    if (i >= N_NODES) return;
    int hid = lane >> 4;
    int hl  = lane & 15;
    float2 fself = __half22float2(
        *(const __half2*)(g_feath + ((size_t)i << 5) + (hl << 1)));

    int   len[N_ETYPES];
    float ivv[N_ETYPES];
    int4  hd[N_ETYPES];
#pragma unroll
    for (int e = 0; e < N_ETYPES; e++) {
        int seg = e * N_NODES + i;
        int dg  = (int)g_deg[seg];
        len[e] = min(dg, CAP);
        ivv[e] = __fdividef(1.f, (float)dg + 1.f);
        hd[e]  = __ldg((const int4*)(g_eidx + (size_t)seg * CAP));
    }
#pragma unroll
    for (int e = 0; e < N_ETYPES; e++) {
        const int* lst = g_eidx + (size_t)(e * N_NODES + i) * CAP;
        int l  = len[e];
        int l4 = l & ~3;
        float2 s = make_float2(0.f, 0.f);
        int4 v = hd[e];
        for (int k = 0; k < l4; k += 4) {
            int4 nv;
            if (k + 4 < l4) nv = __ldg((const int4*)(lst + k + 4));
            int ia = hid ? v.y : v.x;
            int ib = hid ? v.w : v.z;
            float2 fa = __half22float2(
                *(const __half2*)(g_feath + ((size_t)ia << 5) + (hl << 1)));
            float2 fb = __half22float2(
                *(const __half2*)(g_feath + ((size_t)ib << 5) + (hl << 1)));
            s.x += fa.x + fb.x;
            s.y += fa.y + fb.y;
            v = nv;
        }
        for (int k = l4; k < l; k += 2) {
            int ea = __ldg(lst + k);
            bool bv = (k + 1 < l);
            int eb = bv ? __ldg(lst + k + 1) : ea;
            int idx = hid ? eb : ea;
            float2 f = __half22float2(
                *(const __half2*)(g_feath + ((size_t)idx << 5) + (hl << 1)));
            if (hid && !bv) { f.x = 0.f; f.y = 0.f; }
            s.x += f.x; s.y += f.y;
        }
        s.x += __shfl_down_sync(0xffffffffu, s.x, 16);
        s.y += __shfl_down_sync(0xffffffffu, s.y, 16);
        if (lane < 12) {
            float y0 = (s.x + fself.x) * ivv[e];
            float y1 = (s.y + fself.y) * ivv[e];
            *(__half2*)(g_y + ((size_t)i << 7) + e * 24 + (lane << 1)) =
                __floats2half2_rn(y0, y1);
        }
    }
}

// ---------------- kernel 2: layer-1 GEMM via wmma, fp8 epilogue ------------
#define GM_NODES 64
#define AS_LD 136
__global__ void __launch_bounds__(256) k_gemm(const float* __restrict__ b1) {
    extern __shared__ char smraw[];
    __half* As = (__half*)smraw;                 // 64 x 136
    __half* Bs = As + 64 * AS_LD;                // 128 x 136
    float*  Cst = (float*)smraw;                 // 64 x 128 f32 (reuse)
    __shared__ float bs[HID_DIM];
    int tid = threadIdx.x;
    int nb  = blockIdx.x * GM_NODES;

    if (tid < HID_DIM) {
        float s = 0.f;
#pragma unroll
        for (int e = 0; e < N_ETYPES; e++) s += b1[e * HID_DIM + tid];
        bs[tid] = s;
    }
    for (int q = tid; q < 64 * 16; q += 256) {
        int r = q >> 4, sg = q & 15;
        uint4 v = make_uint4(0u, 0u, 0u, 0u);
        int node = nb + r;
        if (node < N_NODES) v = *(const uint4*)(g_y + ((size_t)node << 7) + sg * 8);
        *(uint4*)(As + r * AS_LD + sg * 8) = v;
    }
    for (int q = tid; q < 128 * 16; q += 256) {
        int r = q >> 4, sg = q & 15;
        *(uint4*)(Bs + r * AS_LD + sg * 8) = *(const uint4*)(g_W1h + r * 128 + sg * 8);
    }
    __syncthreads();

    int w    = tid >> 5;
    int rowB = (w >> 1) * 16;
    int colB = (w & 1) * 64;
    wmma::fragment<wmma::accumulator, 16, 16, 16, float> c[4];
#pragma unroll
    for (int j = 0; j < 4; j++) wmma::fill_fragment(c[j], 0.f);
#pragma unroll
    for (int k0 = 0; k0 < 8; k0++) {
        wmma::fragment<wmma::matrix_a, 16, 16, 16, __half, wmma::row_major> a;
        wmma::load_matrix_sync(a, As + rowB * AS_LD + k0 * 16, AS_LD);
#pragma unroll
        for (int j = 0; j < 4; j++) {
            wmma::fragment<wmma::matrix_b, 16, 16, 16, __half, wmma::row_major> b;
            wmma::load_matrix_sync(b, Bs + (k0 * 16) * AS_LD + colB + j * 16, AS_LD);
            wmma::mma_sync(c[j], a, b, c[j]);
        }
    }
    __syncthreads();
#pragma unroll
    for (int j = 0; j < 4; j++)
        wmma::store_matrix_sync(Cst + rowB * 128 + colB + j * 16, c[j], 128,
                                wmma::mem_row_major);
    __syncthreads();
    // epilogue: bias + relu + pack fp8 e4m3 (explicit byte order: dim 4p -> low)
    for (int q = tid; q < 64 * 32; q += 256) {
        int r = q >> 5, p = q & 31;
        int node = nb + r;
        if (node >= N_NODES) continue;
        float v0 = fmaxf(Cst[r * 128 + 4 * p]     + bs[4 * p],     0.f);
        float v1 = fmaxf(Cst[r * 128 + 4 * p + 1] + bs[4 * p + 1], 0.f);
        float v2 = fmaxf(Cst[r * 128 + 4 * p + 2] + bs[4 * p + 2], 0.f);
        float v3 = fmaxf(Cst[r * 128 + 4 * p + 3] + bs[4 * p + 3], 0.f);
        unsigned b0 = __nv_cvt_float_to_fp8(v0, __NV_SATFINITE, __NV_E4M3);
        unsigned b1w = __nv_cvt_float_to_fp8(v1, __NV_SATFINITE, __NV_E4M3);
        unsigned b2 = __nv_cvt_float_to_fp8(v2, __NV_SATFINITE, __NV_E4M3);
        unsigned b3 = __nv_cvt_float_to_fp8(v3, __NV_SATFINITE, __NV_E4M3);
        g_h1b[((size_t)node << 5) + p] = b0 | (b1w << 8) | (b2 << 16) | (b3 << 24);
    }
}

// ---------------- kernel 3 (PROFILED): layer 2 — fp8 gather ----------------
// Lane owns dims 4*lane..4*lane+3. Per edge: one LDG.32 (128B/warp = 1 line),
// 2 cvt, 2 hadd2. inv inline from g_deg.
#define L2CH 64
__global__ void __launch_bounds__(256, 4) k_layer2(const int* __restrict__ gid) {
    __shared__ float sacc[8][N_ETYPES * HID_DIM];   // 20 KB
    int tid  = threadIdx.x;
    int lane = tid & 31;
    int w    = tid >> 5;
    int start = blockIdx.x * L2CH;
    int end   = min(start + L2CH, N_NODES);
    int g0 = gid[start];
    bool multi = (gid[end - 1] != g0);

    float4 acc[N_ETYPES];
#pragma unroll
    for (int e = 0; e < N_ETYPES; e++) acc[e] = make_float4(0.f, 0.f, 0.f, 0.f);
    int gcur = g0;

    for (int i = start + w; i < end; i += 8) {
        int g = gid[i];
        if (multi && g != gcur) {
#pragma unroll
            for (int e = 0; e < N_ETYPES; e++) {
                float* p = g_S + (size_t)(e * NUM_GRAPHS + gcur) * HID_DIM + lane * 4;
                if (acc[e].x != 0.f) atomicAdd(p + 0, acc[e].x);
                if (acc[e].y != 0.f) atomicAdd(p + 1, acc[e].y);
                if (acc[e].z != 0.f) atomicAdd(p + 2, acc[e].z);
                if (acc[e].w != 0.f) atomicAdd(p + 3, acc[e].w);
                acc[e] = make_float4(0.f, 0.f, 0.f, 0.f);
            }
            gcur = g;
        }
        unsigned rs = __ldg(&g_h1b[((size_t)i << 5) + lane]);
        __half2 self0, self1;
        fp8x4_to_h2(rs, self0, self1);

#pragma unroll
        for (int e = 0; e < N_ETYPES; e++) {
            int seg = e * N_NODES + i;
            int dg  = (int)g_deg[seg];
            int l   = min(dg, CAP);
            float iv = __fdividef(1.f, (float)dg + 1.f);
            const int* lst = g_eidx + (size_t)seg * CAP;
            int l4 = l & ~3;
            __half2 u0 = self0, u1 = self1;
            int4 v = __ldg((const int4*)lst);
            for (int k = 0; k < l4; k += 4) {
                int4 nv;
                if (k + 4 < l4) nv = __ldg((const int4*)(lst + k + 4));
                unsigned ra = __ldg(&g_h1b[((size_t)v.x << 5) + lane]);
                unsigned rb = __ldg(&g_h1b[((size_t)v.y << 5) + lane]);
                unsigned rc = __ldg(&g_h1b[((size_t)v.z << 5) + lane]);
                unsigned rd = __ldg(&g_h1b[((size_t)v.w << 5) + lane]);
                __half2 a0, a1, b0, b1v, c0, c1, d0, d1;
                fp8x4_to_h2(ra, a0, a1);
                fp8x4_to_h2(rb, b0, b1v);
                fp8x4_to_h2(rc, c0, c1);
                fp8x4_to_h2(rd, d0, d1);
                u0 = __hadd2(u0, __hadd2(__hadd2(a0, b0), __hadd2(c0, d0)));
                u1 = __hadd2(u1, __hadd2(__hadd2(a1, b1v), __hadd2(c1, d1)));
                v = nv;
            }
            for (int k = l4; k < l; k++) {
                int a = __ldg(lst + k);
                unsigned ra = __ldg(&g_h1b[((size_t)a << 5) + lane]);
                __half2 a0, a1;
                fp8x4_to_h2(ra, a0, a1);
                u0 = __hadd2(u0, a0);
                u1 = __hadd2(u1, a1);
            }
            float2 f0 = __half22float2(u0);
            float2 f1 = __half22float2(u1);
            acc[e].x = fmaf(f0.x, iv, acc[e].x);
            acc[e].y = fmaf(f0.y, iv, acc[e].y);
            acc[e].z = fmaf(f1.x, iv, acc[e].z);
            acc[e].w = fmaf(f1.y, iv, acc[e].w);
        }
    }

    if (multi) {
#pragma unroll
        for (int e = 0; e < N_ETYPES; e++) {
            float* p = g_S + (size_t)(e * NUM_GRAPHS + gcur) * HID_DIM + lane * 4;
            if (acc[e].x != 0.f) atomicAdd(p + 0, acc[e].x);
            if (acc[e].y != 0.f) atomicAdd(p + 1, acc[e].y);
            if (acc[e].z != 0.f) atomicAdd(p + 2, acc[e].z);
            if (acc[e].w != 0.f) atomicAdd(p + 3, acc[e].w);
        }
    } else {
#pragma unroll
        for (int e = 0; e < N_ETYPES; e++)
            *(float4*)&sacc[w][e * HID_DIM + lane * 4] = acc[e];
        __syncthreads();
        for (int q = tid; q < N_ETYPES * HID_DIM; q += 256) {
            float s = 0.f;
#pragma unroll
            for (int w2 = 0; w2 < 8; w2++) s += sacc[w2][q];
            if (s != 0.f) {
                int e = q >> 7, d = q & 127;
                atomicAdd(&g_S[(size_t)(e * NUM_GRAPHS + g0) * HID_DIM + d], s);
            }
        }
    }
}

// ---------------- kernel 4: finisher + restore deg==0 invariant ------------
#define FIN_BLOCKS 576
__global__ void k_final(const float* __restrict__ W2, const float* __restrict__ b2,
                        float* __restrict__ out) {
    int g = blockIdx.x;
    int o = threadIdx.x;
    if (g < NUM_GRAPHS) {
        __shared__ float Ss[HID_DIM];
        float a = 0.f;
        for (int e = 0; e < N_ETYPES; e++) {
            __syncthreads();
            if (o < HID_DIM) Ss[o] = g_S[(e * NUM_GRAPHS + g) * HID_DIM + o];
            __syncthreads();
            if (o < OUT_DIM) {
                const float* We = W2 + (size_t)e * HID_DIM * OUT_DIM;
#pragma unroll 4
                for (int k = 0; k < HID_DIM; k++)
                    a = fmaf(Ss[k], We[k * OUT_DIM + o], a);
            }
        }
        if (o < OUT_DIM) {
            int cnt = g_gstart[g + 1] - g_gstart[g];
            float bsum = 0.f;
#pragma unroll
            for (int e = 0; e < N_ETYPES; e++) bsum += b2[e * OUT_DIM + o];
            out[g * OUT_DIM + o] = (cnt > 0) ? (a / (float)cnt + bsum) : 0.f;
        }
    }
    for (int q = blockIdx.x * blockDim.x + threadIdx.x; q < TOT_SEG;
         q += FIN_BLOCKS * blockDim.x)
        g_deg[q] = 0u;
}

// ---------------- launcher ---------------------------------------------------
extern "C" void kernel_launch(void* const* d_in, const int* in_sizes, int n_in,
                              void* d_out, int out_size) {
    const float* feat = (const float*)d_in[0];
    const int*   src  = (const int*)  d_in[1];
    const int*   dst  = (const int*)  d_in[2];
    const int*   gid  = (const int*)  d_in[3];
    const float* W1   = (const float*)d_in[4];
    const float* b1   = (const float*)d_in[5];
    const float* W2   = (const float*)d_in[6];
    const float* b2   = (const float*)d_in[7];
    float* out = (float*)d_out;

    k_build<<<(TOT_EDGES + 255) / 256, 256>>>(src, dst, feat, W1, gid); // 0
    k_agg<<<(N_NODES * 32 + 255) / 256, 256>>>();                        // 1

    int gsm = 64 * AS_LD * 2 + 128 * AS_LD * 2;                          // 52224 B
    cudaFuncSetAttribute(k_gemm, cudaFuncAttributeMaxDynamicSharedMemorySize, gsm);
    k_gemm<<<(N_NODES + GM_NODES - 1) / GM_NODES, 256, gsm>>>(b1);       // 2

    k_layer2<<<(N_NODES + L2CH - 1) / L2CH, 256>>>(gid);                 // 3 (profiled)
    k_final<<<FIN_BLOCKS, 128>>>(W2, b2, out);                           // 4
}